// round 1
// baseline (speedup 1.0000x reference)
#include <cuda_runtime.h>
#include <cstdint>
#include <math.h>

#define DI __device__ __forceinline__

// Problem dims
constexpr int Bn = 4, Tn = 4096, Hn = 1024, Sn = 64;
constexpr int Mn = Bn * Tn;             // 16384 rows
constexpr int CH = 128, NCH = Tn / CH;  // chunked scan: 128 per chunk, 32 chunks

// ---------------- scratch (static device memory; no allocations) -------------
__device__ float g_P[Mn * 128];          // proj results [M,128] (gate|Bx)   8MB
__device__ float g_u[Mn * Sn];           // u, overwritten in-place by local scan 4MB
__device__ float g_last[Bn * NCH * Sn];  // chunk-final local states
__device__ float g_carry[Bn * NCH * Sn]; // carry-in per chunk
__device__ float g_decay[CH * Sn];       // A^(j+1) table
__device__ float g_wct[Sn * Hn];         // WC transposed [S,H]
__device__ float g_hn[Mn * Hn];          // LayerNorm output (fp32)          64MB

// ---------------- helpers ----------------------------------------------------
DI float tf32r(float x) {
    uint32_t u;
    asm("cvt.rna.tf32.f32 %0, %1;" : "=r"(u) : "f"(x));
    return __uint_as_float(u);
}

DI void mma_tf32(float4& c, const uint32_t a[4], const uint32_t b[2]) {
    asm volatile(
        "mma.sync.aligned.m16n8k8.row.col.f32.tf32.tf32.f32 "
        "{%0,%1,%2,%3}, {%4,%5,%6,%7}, {%8,%9}, {%0,%1,%2,%3};"
        : "+f"(c.x), "+f"(c.y), "+f"(c.z), "+f"(c.w)
        : "r"(a[0]), "r"(a[1]), "r"(a[2]), "r"(a[3]), "r"(b[0]), "r"(b[1]));
}

// ---------------- K0: transpose WC + decay table ------------------------------
__global__ void k_prep(const float* __restrict__ WC, const float* __restrict__ A_log) {
    int i = blockIdx.x * blockDim.x + threadIdx.x;
    if (i < Sn * Hn) {
        int h = i / Sn, s = i % Sn;
        g_wct[s * Hn + h] = WC[i];
    }
    if (i < CH * Sn) {
        int j = i / Sn, s = i % Sn;
        g_decay[i] = expf((float)(j + 1) * A_log[s]);
    }
}

// ---------------- K1: P = x @ [Wg;WB]^T   (M=16384, N=128, K=1024) -----------
// BM=64, BN=128, BK=32, 256 threads, TM=4, TN=8  (fp32 SIMT)
__global__ void __launch_bounds__(256) k_proj(const float* __restrict__ x,
                                              const float* __restrict__ Wg,
                                              const float* __restrict__ WB) {
    __shared__ float As[32][64];   // [k][m]
    __shared__ float Bs[32][128];  // [k][n]
    const int tid = threadIdx.x;
    const int m0 = blockIdx.x * 64;
    const int ty = tid >> 4, tx = tid & 15;

    float acc[4][8];
#pragma unroll
    for (int i = 0; i < 4; i++)
#pragma unroll
        for (int j = 0; j < 8; j++) acc[i][j] = 0.f;

    for (int k0 = 0; k0 < Hn; k0 += 32) {
#pragma unroll
        for (int li = 0; li < 2; li++) {   // x tile: 64x32
            int idx = tid + li * 256;
            int r = idx >> 3, kq = (idx & 7) * 4;
            float4 v = *(const float4*)(x + (size_t)(m0 + r) * Hn + k0 + kq);
            As[kq + 0][r] = v.x; As[kq + 1][r] = v.y;
            As[kq + 2][r] = v.z; As[kq + 3][r] = v.w;
        }
#pragma unroll
        for (int li = 0; li < 4; li++) {   // W tile: 128x32 (rows 0-63: Wg, 64-127: WB)
            int idx = tid + li * 256;
            int n = idx >> 3, kq = (idx & 7) * 4;
            const float* Wr = (n < 64) ? (Wg + (size_t)n * Hn) : (WB + (size_t)(n - 64) * Hn);
            float4 v = *(const float4*)(Wr + k0 + kq);
            Bs[kq + 0][n] = v.x; Bs[kq + 1][n] = v.y;
            Bs[kq + 2][n] = v.z; Bs[kq + 3][n] = v.w;
        }
        __syncthreads();
#pragma unroll
        for (int k = 0; k < 32; k++) {
            float4 a  = *(const float4*)&As[k][ty * 4];
            float4 b0 = *(const float4*)&Bs[k][tx * 8];
            float4 b1 = *(const float4*)&Bs[k][tx * 8 + 4];
            float av[4] = {a.x, a.y, a.z, a.w};
            float bv[8] = {b0.x, b0.y, b0.z, b0.w, b1.x, b1.y, b1.z, b1.w};
#pragma unroll
            for (int i = 0; i < 4; i++)
#pragma unroll
                for (int j = 0; j < 8; j++)
                    acc[i][j] = fmaf(av[i], bv[j], acc[i][j]);
        }
        __syncthreads();
    }
#pragma unroll
    for (int i = 0; i < 4; i++) {
        float* prow = g_P + (size_t)(m0 + ty * 4 + i) * 128 + tx * 8;
        *(float4*)prow       = make_float4(acc[i][0], acc[i][1], acc[i][2], acc[i][3]);
        *(float4*)(prow + 4) = make_float4(acc[i][4], acc[i][5], acc[i][6], acc[i][7]);
    }
}

// ---------------- K1b: u = sigmoid(Pg + bg) * Pb ------------------------------
__global__ void k_u(const float* __restrict__ bg) {
    int i = blockIdx.x * 256 + threadIdx.x;  // over Mn*Sn = 1M
    int s = i & 63;
    int row = i >> 6;
    float gl = g_P[row * 128 + s] + bg[s];
    float bx = g_P[row * 128 + 64 + s];
    float gate = 1.f / (1.f + __expf(-gl));
    g_u[i] = gate * bx;
}

// ---------------- K2: local chunk scans (in-place on g_u) ---------------------
__global__ void k_scan(const float* __restrict__ A_log) {
    int b = blockIdx.x >> 5;   // / NCH(32)
    int c = blockIdx.x & 31;
    int s = threadIdx.x;       // 64 threads
    float A = expf(A_log[s]);
    float* base = g_u + (size_t)(b * Tn + c * CH) * Sn + s;

    float st = 0.f;
    float p0 = base[0 * 64], p1 = base[1 * 64], p2 = base[2 * 64], p3 = base[3 * 64];
#pragma unroll 1
    for (int j = 0; j < CH; j += 4) {
        float n0 = 0.f, n1 = 0.f, n2 = 0.f, n3 = 0.f;
        int jn = j + 4;
        if (jn < CH) {
            n0 = base[(jn + 0) * 64]; n1 = base[(jn + 1) * 64];
            n2 = base[(jn + 2) * 64]; n3 = base[(jn + 3) * 64];
        }
        st = fmaf(A, st, p0); base[(j + 0) * 64] = st;
        st = fmaf(A, st, p1); base[(j + 1) * 64] = st;
        st = fmaf(A, st, p2); base[(j + 2) * 64] = st;
        st = fmaf(A, st, p3); base[(j + 3) * 64] = st;
        p0 = n0; p1 = n1; p2 = n2; p3 = n3;
    }
    g_last[(b * NCH + c) * Sn + s] = st;
}

// ---------------- K2b: sequential carry combine + final_state -----------------
__global__ void k_carry(float* __restrict__ out_tail, int write_tail) {
    int tid = threadIdx.x;  // 256 = B*S chains
    int b = tid >> 6, s = tid & 63;
    float AC = g_decay[(CH - 1) * Sn + s];  // A^CH
    float full = 0.f;
#pragma unroll 1
    for (int c = 0; c < NCH; c++) {
        g_carry[(b * NCH + c) * Sn + s] = full;
        full = fmaf(AC, full, g_last[(b * NCH + c) * Sn + s]);
    }
    if (write_tail) out_tail[b * Sn + s] = full;
}

// ---------------- K3: states fixup -> y = states@WC^T + (D+1)x -> LN -> g_hn --
// Block handles 16 rows (t) x all 1024 h. 256 threads, 4 h per thread.
__global__ void __launch_bounds__(256) k_y_ln(const float* __restrict__ x,
                                              const float* __restrict__ D,
                                              const float* __restrict__ gamma,
                                              const float* __restrict__ beta) {
    __shared__ float sst[16][64];
    __shared__ float ssum[16][8], ssq[16][8];
    const int tid = threadIdx.x;
    const int bt0 = blockIdx.x * 16;

    // fixed-up states for 16 rows
#pragma unroll
    for (int li = 0; li < 4; li++) {
        int idx = tid + li * 256;
        int t = idx >> 6, s = idx & 63;
        int gt = bt0 + t;
        int b = gt >> 12;          // / 4096
        int tt = gt & (Tn - 1);
        int c = tt >> 7, j = tt & 127;
        float v = g_u[gt * 64 + s] + g_decay[j * 64 + s] * g_carry[(b * NCH + c) * 64 + s];
        sst[t][s] = v;
    }
    __syncthreads();

    const int h0 = tid * 4;
    float4 acc[16];
#pragma unroll
    for (int t = 0; t < 16; t++) acc[t] = make_float4(0.f, 0.f, 0.f, 0.f);

    const float4* wct4 = (const float4*)g_wct;
    float4 wc = wct4[tid];  // s = 0
#pragma unroll 1
    for (int s = 0; s < 64; s++) {
        float4 wcn = wc;
        if (s < 63) wcn = wct4[(s + 1) * 256 + tid];
#pragma unroll
        for (int t = 0; t < 16; t++) {
            float f = sst[t][s];
            acc[t].x = fmaf(f, wc.x, acc[t].x);
            acc[t].y = fmaf(f, wc.y, acc[t].y);
            acc[t].z = fmaf(f, wc.z, acc[t].z);
            acc[t].w = fmaf(f, wc.w, acc[t].w);
        }
        wc = wcn;
    }

    const float4 D4 = *(const float4*)(D + h0);
    const float4 g4 = *(const float4*)(gamma + h0);
    const float4 b4 = *(const float4*)(beta + h0);
    const int lane = tid & 31, warp = tid >> 5;

#pragma unroll
    for (int t = 0; t < 16; t++) {
        int gt = bt0 + t;
        float4 xv = *(const float4*)(x + (size_t)gt * Hn + h0);
        float4 hv;
        hv.x = acc[t].x + (D4.x + 1.f) * xv.x;
        hv.y = acc[t].y + (D4.y + 1.f) * xv.y;
        hv.z = acc[t].z + (D4.z + 1.f) * xv.z;
        hv.w = acc[t].w + (D4.w + 1.f) * xv.w;
        acc[t] = hv;
        float s1 = hv.x + hv.y + hv.z + hv.w;
        float s2 = hv.x * hv.x + hv.y * hv.y + hv.z * hv.z + hv.w * hv.w;
#pragma unroll
        for (int off = 16; off; off >>= 1) {
            s1 += __shfl_xor_sync(0xffffffffu, s1, off);
            s2 += __shfl_xor_sync(0xffffffffu, s2, off);
        }
        if (lane == 0) { ssum[t][warp] = s1; ssq[t][warp] = s2; }
    }
    __syncthreads();

#pragma unroll
    for (int t = 0; t < 16; t++) {
        float S1 = 0.f, S2 = 0.f;
#pragma unroll
        for (int w = 0; w < 8; w++) { S1 += ssum[t][w]; S2 += ssq[t][w]; }
        float mu = S1 * (1.f / 1024.f);
        float var = S2 * (1.f / 1024.f) - mu * mu;
        float rs = rsqrtf(var + 1e-5f);
        float4 hv = acc[t];
        float4 o;
        o.x = (hv.x - mu) * rs * g4.x + b4.x;
        o.y = (hv.y - mu) * rs * g4.y + b4.y;
        o.z = (hv.z - mu) * rs * g4.z + b4.z;
        o.w = (hv.w - mu) * rs * g4.w + b4.w;
        *(float4*)(g_hn + (size_t)(bt0 + t) * Hn + h0) = o;
    }
}

// ---------------- K4: out = hn @ Wout^T + bout  (tf32 mma.sync) ---------------
// BM=128, BN=128, BK=32; 8 warps in 2(M)x4(N); warp tile 64x32 (4x4 m16n8k8)
constexpr int PAD = 36;
__global__ void __launch_bounds__(256) k_out(const float* __restrict__ Wout,
                                             const float* __restrict__ bout,
                                             float* __restrict__ out) {
    __shared__ float As[128][PAD];  // hn tile, rows m, k contiguous
    __shared__ float Bs[128][PAD];  // Wout tile, rows n, k contiguous
    const int tid = threadIdx.x;
    const int lane = tid & 31, warp = tid >> 5;
    const int g = lane >> 2, tig = lane & 3;
    const int wm = warp >> 2, wn = warp & 3;
    const int m0 = blockIdx.y * 128, n0 = blockIdx.x * 128;

    float4 c[4][4];
#pragma unroll
    for (int mt = 0; mt < 4; mt++)
#pragma unroll
        for (int nt = 0; nt < 4; nt++) c[mt][nt] = make_float4(0.f, 0.f, 0.f, 0.f);

    for (int k0 = 0; k0 < 1024; k0 += 32) {
#pragma unroll
        for (int li = 0; li < 4; li++) {
            int idx = tid + li * 256;
            int r = idx >> 3, kq = (idx & 7) * 4;
            float4 v = *(const float4*)(g_hn + (size_t)(m0 + r) * 1024 + k0 + kq);
            float4 w = make_float4(tf32r(v.x), tf32r(v.y), tf32r(v.z), tf32r(v.w));
            *(float4*)&As[r][kq] = w;
            float4 v2 = *(const float4*)(Wout + (size_t)(n0 + r) * 1024 + k0 + kq);
            float4 w2 = make_float4(tf32r(v2.x), tf32r(v2.y), tf32r(v2.z), tf32r(v2.w));
            *(float4*)&Bs[r][kq] = w2;
        }
        __syncthreads();
#pragma unroll
        for (int kk = 0; kk < 4; kk++) {
            const int kb = kk * 8;
            uint32_t aF[4][4], bF[4][2];
#pragma unroll
            for (int mt = 0; mt < 4; mt++) {
                const int r = wm * 64 + mt * 16;
                aF[mt][0] = __float_as_uint(As[r + g][kb + tig]);
                aF[mt][1] = __float_as_uint(As[r + g + 8][kb + tig]);
                aF[mt][2] = __float_as_uint(As[r + g][kb + tig + 4]);
                aF[mt][3] = __float_as_uint(As[r + g + 8][kb + tig + 4]);
            }
#pragma unroll
            for (int nt = 0; nt < 4; nt++) {
                const int cn = wn * 32 + nt * 8 + g;
                bF[nt][0] = __float_as_uint(Bs[cn][kb + tig]);
                bF[nt][1] = __float_as_uint(Bs[cn][kb + tig + 4]);
            }
#pragma unroll
            for (int mt = 0; mt < 4; mt++)
#pragma unroll
                for (int nt = 0; nt < 4; nt++)
                    mma_tf32(c[mt][nt], aF[mt], bF[nt]);
        }
        __syncthreads();
    }

#pragma unroll
    for (int mt = 0; mt < 4; mt++) {
        int r0 = m0 + wm * 64 + mt * 16 + g;
#pragma unroll
        for (int nt = 0; nt < 4; nt++) {
            int cn = n0 + wn * 32 + nt * 8 + tig * 2;
            float2 bo = *(const float2*)(bout + cn);
            float2 o0 = {c[mt][nt].x + bo.x, c[mt][nt].y + bo.y};
            float2 o1 = {c[mt][nt].z + bo.x, c[mt][nt].w + bo.y};
            *(float2*)(out + (size_t)r0 * 1024 + cn) = o0;
            *(float2*)(out + (size_t)(r0 + 8) * 1024 + cn) = o1;
        }
    }
}

// ---------------- launch ------------------------------------------------------
extern "C" void kernel_launch(void* const* d_in, const int* in_sizes, int n_in,
                              void* d_out, int out_size) {
    const float* x     = (const float*)d_in[0];
    const float* A_log = (const float*)d_in[1];
    const float* WB    = (const float*)d_in[2];
    const float* WC    = (const float*)d_in[3];
    const float* D     = (const float*)d_in[4];
    const float* Wg    = (const float*)d_in[5];
    const float* bg    = (const float*)d_in[6];
    const float* Wout  = (const float*)d_in[7];
    const float* bout  = (const float*)d_in[8];
    const float* gamma = (const float*)d_in[9];
    const float* beta  = (const float*)d_in[10];
    float* out = (float*)d_out;

    k_prep<<<256, 256>>>(WC, A_log);
    k_proj<<<Mn / 64, 256>>>(x, Wg, WB);
    k_u<<<(Mn * Sn) / 256, 256>>>(bg);
    k_scan<<<Bn * NCH, 64>>>(A_log);
    int wt = (out_size >= Mn * Hn + Bn * Sn) ? 1 : 0;
    k_carry<<<1, 256>>>(out + (size_t)Mn * Hn, wt);
    k_y_ln<<<Mn / 16, 256>>>(x, D, gamma, beta);
    k_out<<<dim3(8, 128), 256>>>(Wout, bout, out);
}

// round 3
// speedup vs baseline: 1.2413x; 1.2413x over previous
#include <cuda_runtime.h>
#include <cstdint>
#include <math.h>

#define DI __device__ __forceinline__

// Problem dims
constexpr int Bn = 4, Tn = 4096, Hn = 1024, Sn = 64;
constexpr int Mn = Bn * Tn;             // 16384 rows
constexpr int CH = 32, NCH = Tn / CH;   // chunked scan: 32 per chunk, 128 chunks

// ---------------- scratch (static device memory; no allocations) -------------
__device__ float g_u[Mn * Sn];           // u -> local scan states (in place)  4MB
__device__ float g_last[Bn * NCH * Sn];  // chunk-final local states
__device__ float g_carry[Bn * NCH * Sn]; // carry-in per chunk
__device__ float g_decay[CH * Sn];       // A^(j+1) table
__device__ float g_wct[Sn * Hn];         // WC transposed [S,H]
__device__ float g_hn[Mn * Hn];          // LayerNorm output (tf32-rounded)   64MB
__device__ float g_woutr[Hn * Hn];       // Wout tf32-rounded                 4MB

// ---------------- helpers ----------------------------------------------------
DI float tf32r(float x) {
    uint32_t u;
    asm("cvt.rna.tf32.f32 %0, %1;" : "=r"(u) : "f"(x));
    return __uint_as_float(u);
}

DI void mma_tf32(float4& c, const uint32_t a[4], const uint32_t b[2]) {
    asm volatile(
        "mma.sync.aligned.m16n8k8.row.col.f32.tf32.tf32.f32 "
        "{%0,%1,%2,%3}, {%4,%5,%6,%7}, {%8,%9}, {%0,%1,%2,%3};"
        : "+f"(c.x), "+f"(c.y), "+f"(c.z), "+f"(c.w)
        : "r"(a[0]), "r"(a[1]), "r"(a[2]), "r"(a[3]), "r"(b[0]), "r"(b[1]));
}

DI void cp16(void* smem, const void* gmem) {
    uint32_t s = (uint32_t)__cvta_generic_to_shared(smem);
    asm volatile("cp.async.cg.shared.global [%0], [%1], 16;" :: "r"(s), "l"(gmem));
}
DI void cp_commit() { asm volatile("cp.async.commit_group;"); }
DI void cp_wait_all() { asm volatile("cp.async.wait_group 0;"); }

// ---------------- K0: transpose WC + decay table + round Wout -----------------
__global__ void k_prep(const float* __restrict__ WC, const float* __restrict__ A_log,
                       const float* __restrict__ Wout) {
    int i = blockIdx.x * blockDim.x + threadIdx.x;
    if (i < Sn * Hn) {
        int h = i / Sn, s = i % Sn;
        g_wct[s * Hn + h] = WC[i];
    }
    if (i < CH * Sn) {
        int j = i / Sn, s = i % Sn;
        g_decay[i] = expf((float)(j + 1) * A_log[s]);
    }
    if (i < Hn * Hn) g_woutr[i] = tf32r(Wout[i]);
}

// ---------------- K1: P = x @ [Wg;WB]^T, fused gate -> u ----------------------
// BM=128, BN=128(full N), BK=32; tf32 mma.sync; epilogue computes
// u = sigmoid(gate + bg) * bx and writes g_u. Grid = 128 blocks.
constexpr int PADP = 36;
__global__ void __launch_bounds__(256) k_proj(const float* __restrict__ x,
                                              const float* __restrict__ Wg,
                                              const float* __restrict__ WB,
                                              const float* __restrict__ bg) {
    __shared__ float sm[2 * 128 * PADP];
    float (*As)[PADP] = (float(*)[PADP])sm;
    float (*Bs)[PADP] = (float(*)[PADP])(sm + 128 * PADP);
    const int tid = threadIdx.x;
    const int lane = tid & 31, warp = tid >> 5;
    const int g = lane >> 2, tig = lane & 3;
    const int wm = warp >> 2, wn = warp & 3;
    const int m0 = blockIdx.x * 128;

    float4 c[4][4];
#pragma unroll
    for (int mt = 0; mt < 4; mt++)
#pragma unroll
        for (int nt = 0; nt < 4; nt++) c[mt][nt] = make_float4(0.f, 0.f, 0.f, 0.f);

    for (int k0 = 0; k0 < Hn; k0 += 32) {
#pragma unroll
        for (int li = 0; li < 4; li++) {
            int idx = tid + li * 256;
            int r = idx >> 3, kq = (idx & 7) * 4;
            float4 v = *(const float4*)(x + (size_t)(m0 + r) * Hn + k0 + kq);
            *(float4*)&As[r][kq] = make_float4(tf32r(v.x), tf32r(v.y), tf32r(v.z), tf32r(v.w));
            const float* Wr = (r < 64) ? (Wg + (size_t)r * Hn) : (WB + (size_t)(r - 64) * Hn);
            float4 v2 = *(const float4*)(Wr + k0 + kq);
            *(float4*)&Bs[r][kq] = make_float4(tf32r(v2.x), tf32r(v2.y), tf32r(v2.z), tf32r(v2.w));
        }
        __syncthreads();
#pragma unroll
        for (int kk = 0; kk < 4; kk++) {
            const int kb = kk * 8;
            uint32_t aF[4][4], bF[4][2];
#pragma unroll
            for (int mt = 0; mt < 4; mt++) {
                const int r = wm * 64 + mt * 16;
                aF[mt][0] = __float_as_uint(As[r + g][kb + tig]);
                aF[mt][1] = __float_as_uint(As[r + g + 8][kb + tig]);
                aF[mt][2] = __float_as_uint(As[r + g][kb + tig + 4]);
                aF[mt][3] = __float_as_uint(As[r + g + 8][kb + tig + 4]);
            }
#pragma unroll
            for (int nt = 0; nt < 4; nt++) {
                const int cn = wn * 32 + nt * 8 + g;
                bF[nt][0] = __float_as_uint(Bs[cn][kb + tig]);
                bF[nt][1] = __float_as_uint(Bs[cn][kb + tig + 4]);
            }
#pragma unroll
            for (int mt = 0; mt < 4; mt++)
#pragma unroll
                for (int nt = 0; nt < 4; nt++)
                    mma_tf32(c[mt][nt], aF[mt], bF[nt]);
        }
        __syncthreads();
    }

    // Epilogue: warps wn<2 hold gate cols [0,64); stash to smem, then wn>=2
    // (holding bx cols) compute u = sigmoid(gate+bg)*bx.
    float* gb = sm;  // stride 66, 128x66 region (fits: 128*66 < 2*128*36)
    if (wn < 2) {
#pragma unroll
        for (int mt = 0; mt < 4; mt++) {
            int r0 = wm * 64 + mt * 16 + g;
#pragma unroll
            for (int nt = 0; nt < 4; nt++) {
                int cn = wn * 32 + nt * 8 + tig * 2;
                gb[r0 * 66 + cn] = c[mt][nt].x;
                gb[r0 * 66 + cn + 1] = c[mt][nt].y;
                gb[(r0 + 8) * 66 + cn] = c[mt][nt].z;
                gb[(r0 + 8) * 66 + cn + 1] = c[mt][nt].w;
            }
        }
    }
    __syncthreads();
    if (wn >= 2) {
#pragma unroll
        for (int mt = 0; mt < 4; mt++) {
            int r0 = wm * 64 + mt * 16 + g;
#pragma unroll
            for (int nt = 0; nt < 4; nt++) {
                int s = (wn - 2) * 32 + nt * 8 + tig * 2;
                float2 bgv = *(const float2*)(bg + s);
                float g0 = 1.f / (1.f + __expf(-(gb[r0 * 66 + s] + bgv.x)));
                float g1 = 1.f / (1.f + __expf(-(gb[r0 * 66 + s + 1] + bgv.y)));
                float g2 = 1.f / (1.f + __expf(-(gb[(r0 + 8) * 66 + s] + bgv.x)));
                float g3 = 1.f / (1.f + __expf(-(gb[(r0 + 8) * 66 + s + 1] + bgv.y)));
                float2 u0 = {g0 * c[mt][nt].x, g1 * c[mt][nt].y};
                float2 u1 = {g2 * c[mt][nt].z, g3 * c[mt][nt].w};
                *(float2*)(g_u + (size_t)(m0 + r0) * 64 + s) = u0;
                *(float2*)(g_u + (size_t)(m0 + r0 + 8) * 64 + s) = u1;
            }
        }
    }
}

// ---------------- K2: local chunk scans (in-place on g_u) ---------------------
__global__ void k_scan(const float* __restrict__ A_log) {
    int b = blockIdx.x >> 7;   // / NCH(128)
    int c = blockIdx.x & 127;
    int s = threadIdx.x;       // 64 threads
    float A = expf(A_log[s]);
    float* base = g_u + (size_t)(b * Tn + c * CH) * Sn + s;
    float st = 0.f;
#pragma unroll
    for (int j = 0; j < CH; j++) {
        st = fmaf(A, st, base[j * 64]);
        base[j * 64] = st;
    }
    g_last[(b * NCH + c) * Sn + s] = st;
}

// ---------------- K2b: sequential carry combine + final_state -----------------
__global__ void k_carry(float* __restrict__ out_tail, int write_tail) {
    int tid = threadIdx.x;  // 256 = B*S chains
    int b = tid >> 6, s = tid & 63;
    float AC = g_decay[(CH - 1) * Sn + s];  // A^CH
    float full = 0.f;
#pragma unroll 1
    for (int c = 0; c < NCH; c++) {
        g_carry[(b * NCH + c) * Sn + s] = full;
        full = fmaf(AC, full, g_last[(b * NCH + c) * Sn + s]);
    }
    if (write_tail) out_tail[b * Sn + s] = full;
}

// ---------------- K3: states fixup -> y = states@WC^T + (D+1)x -> LN -> g_hn --
__global__ void __launch_bounds__(256) k_y_ln(const float* __restrict__ x,
                                              const float* __restrict__ D,
                                              const float* __restrict__ gamma,
                                              const float* __restrict__ beta) {
    __shared__ float sst[16][64];
    __shared__ float ssum[16][8], ssq[16][8];
    const int tid = threadIdx.x;
    const int bt0 = blockIdx.x * 16;

#pragma unroll
    for (int li = 0; li < 4; li++) {
        int idx = tid + li * 256;
        int t = idx >> 6, s = idx & 63;
        int gt = bt0 + t;
        int b = gt >> 12;
        int tt = gt & (Tn - 1);
        int c = tt >> 5, j = tt & (CH - 1);
        float v = g_u[(size_t)gt * 64 + s] + g_decay[j * 64 + s] * g_carry[(b * NCH + c) * 64 + s];
        sst[t][s] = v;
    }
    __syncthreads();

    const int h0 = tid * 4;
    float4 acc[16];
#pragma unroll
    for (int t = 0; t < 16; t++) acc[t] = make_float4(0.f, 0.f, 0.f, 0.f);

    const float4* wct4 = (const float4*)g_wct;
    float4 wc = wct4[tid];
#pragma unroll 1
    for (int s = 0; s < 64; s++) {
        float4 wcn = wc;
        if (s < 63) wcn = wct4[(s + 1) * 256 + tid];
#pragma unroll
        for (int t = 0; t < 16; t++) {
            float f = sst[t][s];
            acc[t].x = fmaf(f, wc.x, acc[t].x);
            acc[t].y = fmaf(f, wc.y, acc[t].y);
            acc[t].z = fmaf(f, wc.z, acc[t].z);
            acc[t].w = fmaf(f, wc.w, acc[t].w);
        }
        wc = wcn;
    }

    const float4 D4 = *(const float4*)(D + h0);
    const float4 g4 = *(const float4*)(gamma + h0);
    const float4 b4 = *(const float4*)(beta + h0);
    const int lane = tid & 31, warp = tid >> 5;

#pragma unroll
    for (int t = 0; t < 16; t++) {
        int gt = bt0 + t;
        float4 xv = *(const float4*)(x + (size_t)gt * Hn + h0);
        float4 hv;
        hv.x = acc[t].x + (D4.x + 1.f) * xv.x;
        hv.y = acc[t].y + (D4.y + 1.f) * xv.y;
        hv.z = acc[t].z + (D4.z + 1.f) * xv.z;
        hv.w = acc[t].w + (D4.w + 1.f) * xv.w;
        acc[t] = hv;
        float s1 = hv.x + hv.y + hv.z + hv.w;
        float s2 = hv.x * hv.x + hv.y * hv.y + hv.z * hv.z + hv.w * hv.w;
#pragma unroll
        for (int off = 16; off; off >>= 1) {
            s1 += __shfl_xor_sync(0xffffffffu, s1, off);
            s2 += __shfl_xor_sync(0xffffffffu, s2, off);
        }
        if (lane == 0) { ssum[t][warp] = s1; ssq[t][warp] = s2; }
    }
    __syncthreads();

#pragma unroll
    for (int t = 0; t < 16; t++) {
        float S1 = 0.f, S2 = 0.f;
#pragma unroll
        for (int w = 0; w < 8; w++) { S1 += ssum[t][w]; S2 += ssq[t][w]; }
        float mu = S1 * (1.f / 1024.f);
        float var = S2 * (1.f / 1024.f) - mu * mu;
        float rs = rsqrtf(var + 1e-5f);
        float4 hv = acc[t];
        float4 o;
        o.x = tf32r((hv.x - mu) * rs * g4.x + b4.x);
        o.y = tf32r((hv.y - mu) * rs * g4.y + b4.y);
        o.z = tf32r((hv.z - mu) * rs * g4.z + b4.z);
        o.w = tf32r((hv.w - mu) * rs * g4.w + b4.w);
        *(float4*)(g_hn + (size_t)(bt0 + t) * Hn + h0) = o;
    }
}

// ---------------- K4: out = hn @ Wout^T + bout  (tf32 mma, cp.async 2-stage) --
// BM=128, BN=128, BK=16, 2-stage pipeline. Operands pre-rounded to tf32, so
// no cvt in the hot loop (mma truncation of rounded values is exact).
constexpr int PADK = 20;
__global__ void __launch_bounds__(256) k_out(const float* __restrict__ bout,
                                             float* __restrict__ out) {
    __shared__ float As[2][128][PADK];
    __shared__ float Bs[2][128][PADK];
    const int tid = threadIdx.x;
    const int lane = tid & 31, warp = tid >> 5;
    const int g = lane >> 2, tig = lane & 3;
    const int wm = warp >> 2, wn = warp & 3;
    const int m0 = blockIdx.y * 128, n0 = blockIdx.x * 128;

    // tile = 128 rows x 16 k = 512 float4; 256 threads -> 2 float4 each
    const int r_a = tid >> 2, kq_a = (tid & 3) * 4;      // rows 0..63
    const int r_b = r_a + 64, kq_b = kq_a;               // rows 64..127

    float4 c[4][4];
#pragma unroll
    for (int mt = 0; mt < 4; mt++)
#pragma unroll
        for (int nt = 0; nt < 4; nt++) c[mt][nt] = make_float4(0.f, 0.f, 0.f, 0.f);

    auto issue = [&](int st, int k0) {
        cp16(&As[st][r_a][kq_a], g_hn + (size_t)(m0 + r_a) * 1024 + k0 + kq_a);
        cp16(&As[st][r_b][kq_b], g_hn + (size_t)(m0 + r_b) * 1024 + k0 + kq_b);
        cp16(&Bs[st][r_a][kq_a], g_woutr + (size_t)(n0 + r_a) * 1024 + k0 + kq_a);
        cp16(&Bs[st][r_b][kq_b], g_woutr + (size_t)(n0 + r_b) * 1024 + k0 + kq_b);
        cp_commit();
    };

    issue(0, 0);
    constexpr int NT = 1024 / 16;
    for (int kt = 0; kt < NT; kt++) {
        cp_wait_all();
        __syncthreads();
        if (kt + 1 < NT) issue((kt + 1) & 1, (kt + 1) * 16);
        const int st = kt & 1;
#pragma unroll
        for (int kk = 0; kk < 2; kk++) {
            const int kb = kk * 8;
            uint32_t aF[4][4], bF[4][2];
#pragma unroll
            for (int mt = 0; mt < 4; mt++) {
                const int r = wm * 64 + mt * 16;
                aF[mt][0] = __float_as_uint(As[st][r + g][kb + tig]);
                aF[mt][1] = __float_as_uint(As[st][r + g + 8][kb + tig]);
                aF[mt][2] = __float_as_uint(As[st][r + g][kb + tig + 4]);
                aF[mt][3] = __float_as_uint(As[st][r + g + 8][kb + tig + 4]);
            }
#pragma unroll
            for (int nt = 0; nt < 4; nt++) {
                const int cn = wn * 32 + nt * 8 + g;
                bF[nt][0] = __float_as_uint(Bs[st][cn][kb + tig]);
                bF[nt][1] = __float_as_uint(Bs[st][cn][kb + tig + 4]);
            }
#pragma unroll
            for (int mt = 0; mt < 4; mt++)
#pragma unroll
                for (int nt = 0; nt < 4; nt++)
                    mma_tf32(c[mt][nt], aF[mt], bF[nt]);
        }
    }

#pragma unroll
    for (int mt = 0; mt < 4; mt++) {
        int r0 = m0 + wm * 64 + mt * 16 + g;
#pragma unroll
        for (int nt = 0; nt < 4; nt++) {
            int cn = n0 + wn * 32 + nt * 8 + tig * 2;
            float2 bo = *(const float2*)(bout + cn);
            float2 o0 = {c[mt][nt].x + bo.x, c[mt][nt].y + bo.y};
            float2 o1 = {c[mt][nt].z + bo.x, c[mt][nt].w + bo.y};
            *(float2*)(out + (size_t)r0 * 1024 + cn) = o0;
            *(float2*)(out + (size_t)(r0 + 8) * 1024 + cn) = o1;
        }
    }
}

// ---------------- launch ------------------------------------------------------
extern "C" void kernel_launch(void* const* d_in, const int* in_sizes, int n_in,
                              void* d_out, int out_size) {
    const float* x     = (const float*)d_in[0];
    const float* A_log = (const float*)d_in[1];
    const float* WB    = (const float*)d_in[2];
    const float* WC    = (const float*)d_in[3];
    const float* D     = (const float*)d_in[4];
    const float* Wg    = (const float*)d_in[5];
    const float* bg    = (const float*)d_in[6];
    const float* Wout  = (const float*)d_in[7];
    const float* bout  = (const float*)d_in[8];
    const float* gamma = (const float*)d_in[9];
    const float* beta  = (const float*)d_in[10];
    float* out = (float*)d_out;

    k_prep<<<4096, 256>>>(WC, A_log, Wout);
    k_proj<<<Mn / 128, 256>>>(x, Wg, WB, bg);
    k_scan<<<Bn * NCH, 64>>>(A_log);
    int wt = (out_size >= Mn * Hn + Bn * Sn) ? 1 : 0;
    k_carry<<<1, 256>>>(out + (size_t)Mn * Hn, wt);
    k_y_ln<<<Mn / 16, 256>>>(x, D, gamma, beta);
    k_out<<<dim3(8, 128), 256>>>(bout, out);
}

// round 5
// speedup vs baseline: 1.3972x; 1.1256x over previous
#include <cuda_runtime.h>
#include <cstdint>
#include <math.h>

#define DI __device__ __forceinline__

// Problem dims
constexpr int Bn = 4, Tn = 4096, Hn = 1024, Sn = 64;
constexpr int Mn = Bn * Tn;             // 16384 rows
constexpr int CH = 32, NCH = Tn / CH;   // chunked scan: 32 per chunk, 128 chunks

// ---------------- scratch (static device memory; no allocations) -------------
__device__ float g_u[Mn * Sn];           // u -> local scan states (in place)  4MB
__device__ float g_last[Bn * NCH * Sn];  // chunk-final local states
__device__ float g_carry[Bn * NCH * Sn]; // carry-in per chunk
__device__ float g_decay[CH * Sn];       // A^(j+1) table
__device__ float g_wct[Sn * Hn];         // WC transposed [S,H]
__device__ float g_hn[Mn * Hn];          // LayerNorm output (tf32-rounded)   64MB
__device__ float g_woutr[Hn * Hn];       // Wout tf32-rounded                 4MB

// ---------------- helpers ----------------------------------------------------
DI float tf32r(float x) {
    uint32_t u;
    asm("cvt.rna.tf32.f32 %0, %1;" : "=r"(u) : "f"(x));
    return __uint_as_float(u);
}

DI void mma_tf32(float4& c, const uint32_t a[4], const uint32_t b[2]) {
    asm volatile(
        "mma.sync.aligned.m16n8k8.row.col.f32.tf32.tf32.f32 "
        "{%0,%1,%2,%3}, {%4,%5,%6,%7}, {%8,%9}, {%0,%1,%2,%3};"
        : "+f"(c.x), "+f"(c.y), "+f"(c.z), "+f"(c.w)
        : "r"(a[0]), "r"(a[1]), "r"(a[2]), "r"(a[3]), "r"(b[0]), "r"(b[1]));
}

DI void cp16(void* smem, const void* gmem) {
    uint32_t s = (uint32_t)__cvta_generic_to_shared(smem);
    asm volatile("cp.async.cg.shared.global [%0], [%1], 16;" :: "r"(s), "l"(gmem));
}
DI void cp_commit() { asm volatile("cp.async.commit_group;"); }

// ---------------- K0: transpose WC + decay table + round Wout -----------------
__global__ void k_prep(const float* __restrict__ WC, const float* __restrict__ A_log,
                       const float* __restrict__ Wout) {
    int i = blockIdx.x * blockDim.x + threadIdx.x;
    if (i < Sn * Hn) {
        int h = i / Sn, s = i % Sn;
        g_wct[s * Hn + h] = WC[i];
    }
    if (i < CH * Sn) {
        int j = i / Sn, s = i % Sn;
        g_decay[i] = expf((float)(j + 1) * A_log[s]);
    }
    if (i < Hn * Hn) g_woutr[i] = tf32r(Wout[i]);
}

// ---------------- K1: P = x @ [Wg;WB]^T, fused gate -> u ----------------------
// BM=128, BN=128(full N), BK=32; tf32 mma.sync; epilogue computes
// u = sigmoid(gate + bg) * bx and writes g_u. Grid = 128 blocks.
constexpr int PADP = 36;
__global__ void __launch_bounds__(256) k_proj(const float* __restrict__ x,
                                              const float* __restrict__ Wg,
                                              const float* __restrict__ WB,
                                              const float* __restrict__ bg) {
    __shared__ float sm[2 * 128 * PADP];
    float (*As)[PADP] = (float(*)[PADP])sm;
    float (*Bs)[PADP] = (float(*)[PADP])(sm + 128 * PADP);
    const int tid = threadIdx.x;
    const int lane = tid & 31, warp = tid >> 5;
    const int g = lane >> 2, tig = lane & 3;
    const int wm = warp >> 2, wn = warp & 3;
    const int m0 = blockIdx.x * 128;

    float4 c[4][4];
#pragma unroll
    for (int mt = 0; mt < 4; mt++)
#pragma unroll
        for (int nt = 0; nt < 4; nt++) c[mt][nt] = make_float4(0.f, 0.f, 0.f, 0.f);

    for (int k0 = 0; k0 < Hn; k0 += 32) {
#pragma unroll
        for (int li = 0; li < 4; li++) {
            int idx = tid + li * 256;
            int r = idx >> 3, kq = (idx & 7) * 4;
            float4 v = *(const float4*)(x + (size_t)(m0 + r) * Hn + k0 + kq);
            *(float4*)&As[r][kq] = make_float4(tf32r(v.x), tf32r(v.y), tf32r(v.z), tf32r(v.w));
            const float* Wr = (r < 64) ? (Wg + (size_t)r * Hn) : (WB + (size_t)(r - 64) * Hn);
            float4 v2 = *(const float4*)(Wr + k0 + kq);
            *(float4*)&Bs[r][kq] = make_float4(tf32r(v2.x), tf32r(v2.y), tf32r(v2.z), tf32r(v2.w));
        }
        __syncthreads();
#pragma unroll
        for (int kk = 0; kk < 4; kk++) {
            const int kb = kk * 8;
            uint32_t aF[4][4], bF[4][2];
#pragma unroll
            for (int mt = 0; mt < 4; mt++) {
                const int r = wm * 64 + mt * 16;
                aF[mt][0] = __float_as_uint(As[r + g][kb + tig]);
                aF[mt][1] = __float_as_uint(As[r + g + 8][kb + tig]);
                aF[mt][2] = __float_as_uint(As[r + g][kb + tig + 4]);
                aF[mt][3] = __float_as_uint(As[r + g + 8][kb + tig + 4]);
            }
#pragma unroll
            for (int nt = 0; nt < 4; nt++) {
                const int cn = wn * 32 + nt * 8 + g;
                bF[nt][0] = __float_as_uint(Bs[cn][kb + tig]);
                bF[nt][1] = __float_as_uint(Bs[cn][kb + tig + 4]);
            }
#pragma unroll
            for (int mt = 0; mt < 4; mt++)
#pragma unroll
                for (int nt = 0; nt < 4; nt++)
                    mma_tf32(c[mt][nt], aF[mt], bF[nt]);
        }
        __syncthreads();
    }

    // Epilogue: warps wn<2 hold gate cols [0,64); stash to smem, then wn>=2
    // (holding bx cols) compute u = sigmoid(gate+bg)*bx.
    float* gb = sm;  // stride 66, 128x66 region (fits: 128*66 < 2*128*36)
    if (wn < 2) {
#pragma unroll
        for (int mt = 0; mt < 4; mt++) {
            int r0 = wm * 64 + mt * 16 + g;
#pragma unroll
            for (int nt = 0; nt < 4; nt++) {
                int cn = wn * 32 + nt * 8 + tig * 2;
                gb[r0 * 66 + cn] = c[mt][nt].x;
                gb[r0 * 66 + cn + 1] = c[mt][nt].y;
                gb[(r0 + 8) * 66 + cn] = c[mt][nt].z;
                gb[(r0 + 8) * 66 + cn + 1] = c[mt][nt].w;
            }
        }
    }
    __syncthreads();
    if (wn >= 2) {
#pragma unroll
        for (int mt = 0; mt < 4; mt++) {
            int r0 = wm * 64 + mt * 16 + g;
#pragma unroll
            for (int nt = 0; nt < 4; nt++) {
                int s = (wn - 2) * 32 + nt * 8 + tig * 2;
                float2 bgv = *(const float2*)(bg + s);
                float g0 = 1.f / (1.f + __expf(-(gb[r0 * 66 + s] + bgv.x)));
                float g1 = 1.f / (1.f + __expf(-(gb[r0 * 66 + s + 1] + bgv.y)));
                float g2 = 1.f / (1.f + __expf(-(gb[(r0 + 8) * 66 + s] + bgv.x)));
                float g3 = 1.f / (1.f + __expf(-(gb[(r0 + 8) * 66 + s + 1] + bgv.y)));
                float2 u0 = {g0 * c[mt][nt].x, g1 * c[mt][nt].y};
                float2 u1 = {g2 * c[mt][nt].z, g3 * c[mt][nt].w};
                *(float2*)(g_u + (size_t)(m0 + r0) * 64 + s) = u0;
                *(float2*)(g_u + (size_t)(m0 + r0 + 8) * 64 + s) = u1;
            }
        }
    }
}

// ---------------- K2: local chunk scans (in-place on g_u) ---------------------
__global__ void k_scan(const float* __restrict__ A_log) {
    int b = blockIdx.x >> 7;   // / NCH(128)
    int c = blockIdx.x & 127;
    int s = threadIdx.x;       // 64 threads
    float A = expf(A_log[s]);
    float* base = g_u + (size_t)(b * Tn + c * CH) * Sn + s;
    float st = 0.f;
#pragma unroll
    for (int j = 0; j < CH; j++) {
        st = fmaf(A, st, base[j * 64]);
        base[j * 64] = st;
    }
    g_last[(b * NCH + c) * Sn + s] = st;
}

// ---------------- K2b: parallel affine scan over chunks (Kogge-Stone) ---------
// One block per (b,s) chain, 128 threads = 128 chunks. Composition of
// x -> AC*x + last_c: pairs (p,v) combine as (p2*p1, v2 + p2*v1).
__global__ void __launch_bounds__(128) k_carry(float* __restrict__ out_tail,
                                               int write_tail) {
    __shared__ float wtot[4], wp[4];
    const int chain = blockIdx.x;          // 256 chains = B*S
    const int b = chain >> 6, s = chain & 63;
    const int c = threadIdx.x;             // chunk index 0..127
    const int lane = c & 31, warp = c >> 5;

    const float AC = g_decay[(CH - 1) * Sn + s];   // A^CH
    float v = g_last[(b * NCH + c) * Sn + s];
    float p = AC;
#pragma unroll
    for (int off = 1; off < 32; off <<= 1) {
        float pv = __shfl_up_sync(0xffffffffu, v, off);
        float pp = __shfl_up_sync(0xffffffffu, p, off);
        if (lane >= off) { v = fmaf(p, pv, v); p *= pp; }
    }
    // v = inclusive local scan within warp, p = AC^(lane+1)
    if (lane == 31) { wtot[warp] = v; wp[warp] = p; }
    __syncthreads();
    float cin = 0.f;   // state entering this warp's first chunk
#pragma unroll
    for (int w = 0; w < 3; w++)
        if (w < warp) cin = fmaf(wp[w], cin, wtot[w]);
    float inc = fmaf(p, cin, v);                       // inclusive state at chunk c
    float prev = __shfl_up_sync(0xffffffffu, inc, 1);
    float carry_c = (lane == 0) ? cin : prev;          // exclusive = carry-in
    g_carry[(b * NCH + c) * Sn + s] = carry_c;
    if (c == NCH - 1 && write_tail) out_tail[b * Sn + s] = inc;
}

// ---------------- K3: states fixup -> y = states@WC^T + (D+1)x -> LN -> g_hn --
__global__ void __launch_bounds__(256) k_y_ln(const float* __restrict__ x,
                                              const float* __restrict__ D,
                                              const float* __restrict__ gamma,
                                              const float* __restrict__ beta) {
    __shared__ float sst[16][64];
    __shared__ float ssum[16][8], ssq[16][8];
    const int tid = threadIdx.x;
    const int bt0 = blockIdx.x * 16;

#pragma unroll
    for (int li = 0; li < 4; li++) {
        int idx = tid + li * 256;
        int t = idx >> 6, s = idx & 63;
        int gt = bt0 + t;
        int b = gt >> 12;
        int tt = gt & (Tn - 1);
        int c = tt >> 5, j = tt & (CH - 1);
        float v = g_u[(size_t)gt * 64 + s] + g_decay[j * 64 + s] * g_carry[(b * NCH + c) * 64 + s];
        sst[t][s] = v;
    }
    __syncthreads();

    const int h0 = tid * 4;
    float4 acc[16];
#pragma unroll
    for (int t = 0; t < 16; t++) acc[t] = make_float4(0.f, 0.f, 0.f, 0.f);

    const float4* wct4 = (const float4*)g_wct;
    float4 wc = wct4[tid];
#pragma unroll 1
    for (int s = 0; s < 64; s++) {
        float4 wcn = wc;
        if (s < 63) wcn = wct4[(s + 1) * 256 + tid];
#pragma unroll
        for (int t = 0; t < 16; t++) {
            float f = sst[t][s];
            acc[t].x = fmaf(f, wc.x, acc[t].x);
            acc[t].y = fmaf(f, wc.y, acc[t].y);
            acc[t].z = fmaf(f, wc.z, acc[t].z);
            acc[t].w = fmaf(f, wc.w, acc[t].w);
        }
        wc = wcn;
    }

    const float4 D4 = *(const float4*)(D + h0);
    const float4 g4 = *(const float4*)(gamma + h0);
    const float4 b4 = *(const float4*)(beta + h0);
    const int lane = tid & 31, warp = tid >> 5;

#pragma unroll
    for (int t = 0; t < 16; t++) {
        int gt = bt0 + t;
        float4 xv = *(const float4*)(x + (size_t)gt * Hn + h0);
        float4 hv;
        hv.x = acc[t].x + (D4.x + 1.f) * xv.x;
        hv.y = acc[t].y + (D4.y + 1.f) * xv.y;
        hv.z = acc[t].z + (D4.z + 1.f) * xv.z;
        hv.w = acc[t].w + (D4.w + 1.f) * xv.w;
        acc[t] = hv;
        float s1 = hv.x + hv.y + hv.z + hv.w;
        float s2 = hv.x * hv.x + hv.y * hv.y + hv.z * hv.z + hv.w * hv.w;
#pragma unroll
        for (int off = 16; off; off >>= 1) {
            s1 += __shfl_xor_sync(0xffffffffu, s1, off);
            s2 += __shfl_xor_sync(0xffffffffu, s2, off);
        }
        if (lane == 0) { ssum[t][warp] = s1; ssq[t][warp] = s2; }
    }
    __syncthreads();

#pragma unroll
    for (int t = 0; t < 16; t++) {
        float S1 = 0.f, S2 = 0.f;
#pragma unroll
        for (int w = 0; w < 8; w++) { S1 += ssum[t][w]; S2 += ssq[t][w]; }
        float mu = S1 * (1.f / 1024.f);
        float var = S2 * (1.f / 1024.f) - mu * mu;
        float rs = rsqrtf(var + 1e-5f);
        float4 hv = acc[t];
        float4 o;
        o.x = tf32r((hv.x - mu) * rs * g4.x + b4.x);
        o.y = tf32r((hv.y - mu) * rs * g4.y + b4.y);
        o.z = tf32r((hv.z - mu) * rs * g4.z + b4.z);
        o.w = tf32r((hv.w - mu) * rs * g4.w + b4.w);
        *(float4*)(g_hn + (size_t)(bt0 + t) * Hn + h0) = o;
    }
}

// ---------------- K4: out = hn @ Wout^T + bout  (tf32 mma, 4-stage cp.async) --
// BM=128, BN=128, BK=16. Operands pre-rounded to tf32 (no cvt in hot loop).
constexpr int PADK = 20;
constexpr int KSTG = 4;
constexpr int STG_F = 2 * 128 * PADK;              // floats per stage (A+B)
constexpr int SMEM_KOUT = KSTG * STG_F * 4;        // 81920 bytes
__global__ void __launch_bounds__(256) k_out(const float* __restrict__ bout,
                                             float* __restrict__ out) {
    extern __shared__ float smk[];
    const int tid = threadIdx.x;
    const int lane = tid & 31, warp = tid >> 5;
    const int g = lane >> 2, tig = lane & 3;
    const int wm = warp >> 2, wn = warp & 3;
    const int m0 = blockIdx.y * 128, n0 = blockIdx.x * 128;

    // tile = 128 rows x 16 k = 512 float4; 256 threads -> 2 float4 each
    const int r_a = tid >> 2, kq_a = (tid & 3) * 4;  // rows 0..63
    const int r_b = r_a + 64;                        // rows 64..127

    float4 c[4][4];
#pragma unroll
    for (int mt = 0; mt < 4; mt++)
#pragma unroll
        for (int nt = 0; nt < 4; nt++) c[mt][nt] = make_float4(0.f, 0.f, 0.f, 0.f);

    auto issue = [&](int st, int k0) {
        float* A = smk + st * STG_F;
        float* B = A + 128 * PADK;
        cp16(A + r_a * PADK + kq_a, g_hn + (size_t)(m0 + r_a) * 1024 + k0 + kq_a);
        cp16(A + r_b * PADK + kq_a, g_hn + (size_t)(m0 + r_b) * 1024 + k0 + kq_a);
        cp16(B + r_a * PADK + kq_a, g_woutr + (size_t)(n0 + r_a) * 1024 + k0 + kq_a);
        cp16(B + r_b * PADK + kq_a, g_woutr + (size_t)(n0 + r_b) * 1024 + k0 + kq_a);
        cp_commit();
    };

    issue(0, 0);
    issue(1, 16);
    issue(2, 32);
    constexpr int NT = 1024 / 16;
    for (int kt = 0; kt < NT; kt++) {
        asm volatile("cp.async.wait_group 2;");
        __syncthreads();
        const int st = kt & 3;
        const float* A = smk + st * STG_F;
        const float* B = A + 128 * PADK;
#pragma unroll
        for (int kk = 0; kk < 2; kk++) {
            const int kb = kk * 8;
            uint32_t aF[4][4], bF[4][2];
#pragma unroll
            for (int mt = 0; mt < 4; mt++) {
                const int r = wm * 64 + mt * 16;
                aF[mt][0] = __float_as_uint(A[(r + g) * PADK + kb + tig]);
                aF[mt][1] = __float_as_uint(A[(r + g + 8) * PADK + kb + tig]);
                aF[mt][2] = __float_as_uint(A[(r + g) * PADK + kb + tig + 4]);
                aF[mt][3] = __float_as_uint(A[(r + g + 8) * PADK + kb + tig + 4]);
            }
#pragma unroll
            for (int nt = 0; nt < 4; nt++) {
                const int cn = wn * 32 + nt * 8 + g;
                bF[nt][0] = __float_as_uint(B[cn * PADK + kb + tig]);
                bF[nt][1] = __float_as_uint(B[cn * PADK + kb + tig + 4]);
            }
#pragma unroll
            for (int mt = 0; mt < 4; mt++)
#pragma unroll
                for (int nt = 0; nt < 4; nt++)
                    mma_tf32(c[mt][nt], aF[mt], bF[nt]);
        }
        if (kt + 3 < NT) issue((kt + 3) & 3, (kt + 3) * 16);
        else cp_commit();   // empty group keeps wait_group accounting aligned
    }

#pragma unroll
    for (int mt = 0; mt < 4; mt++) {
        int r0 = m0 + wm * 64 + mt * 16 + g;
#pragma unroll
        for (int nt = 0; nt < 4; nt++) {
            int cn = n0 + wn * 32 + nt * 8 + tig * 2;
            float2 bo = *(const float2*)(bout + cn);
            float2 o0 = {c[mt][nt].x + bo.x, c[mt][nt].y + bo.y};
            float2 o1 = {c[mt][nt].z + bo.x, c[mt][nt].w + bo.y};
            *(float2*)(out + (size_t)r0 * 1024 + cn) = o0;
            *(float2*)(out + (size_t)(r0 + 8) * 1024 + cn) = o1;
        }
    }
}

// ---------------- launch ------------------------------------------------------
extern "C" void kernel_launch(void* const* d_in, const int* in_sizes, int n_in,
                              void* d_out, int out_size) {
    const float* x     = (const float*)d_in[0];
    const float* A_log = (const float*)d_in[1];
    const float* WB    = (const float*)d_in[2];
    const float* WC    = (const float*)d_in[3];
    const float* D     = (const float*)d_in[4];
    const float* Wg    = (const float*)d_in[5];
    const float* bg    = (const float*)d_in[6];
    const float* Wout  = (const float*)d_in[7];
    const float* bout  = (const float*)d_in[8];
    const float* gamma = (const float*)d_in[9];
    const float* beta  = (const float*)d_in[10];
    float* out = (float*)d_out;

    // Unconditional (no static guards — harness forbids call-count-dependent
    // behavior). Idempotent host-side call; enqueues no device work.
    cudaFuncSetAttribute(k_out, cudaFuncAttributeMaxDynamicSharedMemorySize, SMEM_KOUT);

    k_prep<<<4096, 256>>>(WC, A_log, Wout);
    k_proj<<<Mn / 128, 256>>>(x, Wg, WB, bg);
    k_scan<<<Bn * NCH, 64>>>(A_log);
    int wt = (out_size >= Mn * Hn + Bn * Sn) ? 1 : 0;
    k_carry<<<Bn * Sn, 128>>>(out + (size_t)Mn * Hn, wt);
    k_y_ln<<<Mn / 16, 256>>>(x, D, gamma, beta);
    k_out<<<dim3(8, 128), 256, SMEM_KOUT>>>(bout, out);
}

// round 8
// speedup vs baseline: 1.8541x; 1.3270x over previous
#include <cuda_runtime.h>
#include <cuda_fp16.h>
#include <cstdint>
#include <math.h>

#define DI __device__ __forceinline__

// Problem dims
constexpr int Bn = 4, Tn = 4096, Hn = 1024, Sn = 64;
constexpr int Mn = Bn * Tn;             // 16384 rows
constexpr int CH = 32, NCH = Tn / CH;   // chunked scan: 32 per chunk, 128 chunks

// ---------------- scratch (static device memory; no allocations) -------------
__device__ float g_u[Mn * Sn];            // u -> local scan states (in place) 4MB
__device__ float g_last[Bn * NCH * Sn];   // chunk-final local states
__device__ float g_carry[Bn * NCH * Sn];  // carry-in per chunk
__device__ float g_decay[CH * Sn];        // A^(j+1) table
__device__ float g_wct[Sn * Hn];          // WC transposed [S,H]
__device__ __half g_hnh[Mn * Hn];         // LayerNorm output (fp16)         32MB
__device__ __half g_wouth[Hn * Hn];       // Wout fp16                        2MB

// ---------------- helpers ----------------------------------------------------
DI float tf32r(float x) {
    uint32_t u;
    asm("cvt.rna.tf32.f32 %0, %1;" : "=r"(u) : "f"(x));
    return __uint_as_float(u);
}

DI void mma_tf32(float4& c, const uint32_t a[4], const uint32_t b[2]) {
    asm volatile(
        "mma.sync.aligned.m16n8k8.row.col.f32.tf32.tf32.f32 "
        "{%0,%1,%2,%3}, {%4,%5,%6,%7}, {%8,%9}, {%0,%1,%2,%3};"
        : "+f"(c.x), "+f"(c.y), "+f"(c.z), "+f"(c.w)
        : "r"(a[0]), "r"(a[1]), "r"(a[2]), "r"(a[3]), "r"(b[0]), "r"(b[1]));
}

DI void mma_f16(float4& c, const uint32_t a[4], const uint32_t b[2]) {
    asm volatile(
        "mma.sync.aligned.m16n8k16.row.col.f32.f16.f16.f32 "
        "{%0,%1,%2,%3}, {%4,%5,%6,%7}, {%8,%9}, {%0,%1,%2,%3};"
        : "+f"(c.x), "+f"(c.y), "+f"(c.z), "+f"(c.w)
        : "r"(a[0]), "r"(a[1]), "r"(a[2]), "r"(a[3]), "r"(b[0]), "r"(b[1]));
}

DI void cp16(void* smem, const void* gmem) {
    uint32_t s = (uint32_t)__cvta_generic_to_shared(smem);
    asm volatile("cp.async.cg.shared.global [%0], [%1], 16;" :: "r"(s), "l"(gmem));
}
DI void cp_commit() { asm volatile("cp.async.commit_group;"); }

// ---------------- K0: transpose WC + decay table + Wout->fp16 -----------------
__global__ void k_prep(const float* __restrict__ WC, const float* __restrict__ A_log,
                       const float* __restrict__ Wout) {
    int i = blockIdx.x * blockDim.x + threadIdx.x;
    if (i < Sn * Hn) {
        int h = i / Sn, s = i % Sn;
        g_wct[s * Hn + h] = WC[i];
    }
    if (i < CH * Sn) {
        int j = i / Sn, s = i % Sn;
        g_decay[i] = expf((float)(j + 1) * A_log[s]);
    }
    if (i < Hn * Hn) g_wouth[i] = __float2half_rn(Wout[i]);
}

// ---------------- K1: P = x @ [Wg;WB]^T, fused gate -> u (tf32 mma) -----------
constexpr int PADP = 36;
__global__ void __launch_bounds__(256) k_proj(const float* __restrict__ x,
                                              const float* __restrict__ Wg,
                                              const float* __restrict__ WB,
                                              const float* __restrict__ bg) {
    __shared__ float sm[2 * 128 * PADP];
    float (*As)[PADP] = (float(*)[PADP])sm;
    float (*Bs)[PADP] = (float(*)[PADP])(sm + 128 * PADP);
    const int tid = threadIdx.x;
    const int lane = tid & 31, warp = tid >> 5;
    const int g = lane >> 2, tig = lane & 3;
    const int wm = warp >> 2, wn = warp & 3;
    const int m0 = blockIdx.x * 128;

    float4 c[4][4];
#pragma unroll
    for (int mt = 0; mt < 4; mt++)
#pragma unroll
        for (int nt = 0; nt < 4; nt++) c[mt][nt] = make_float4(0.f, 0.f, 0.f, 0.f);

    for (int k0 = 0; k0 < Hn; k0 += 32) {
#pragma unroll
        for (int li = 0; li < 4; li++) {
            int idx = tid + li * 256;
            int r = idx >> 3, kq = (idx & 7) * 4;
            float4 v = *(const float4*)(x + (size_t)(m0 + r) * Hn + k0 + kq);
            *(float4*)&As[r][kq] = make_float4(tf32r(v.x), tf32r(v.y), tf32r(v.z), tf32r(v.w));
            const float* Wr = (r < 64) ? (Wg + (size_t)r * Hn) : (WB + (size_t)(r - 64) * Hn);
            float4 v2 = *(const float4*)(Wr + k0 + kq);
            *(float4*)&Bs[r][kq] = make_float4(tf32r(v2.x), tf32r(v2.y), tf32r(v2.z), tf32r(v2.w));
        }
        __syncthreads();
#pragma unroll
        for (int kk = 0; kk < 4; kk++) {
            const int kb = kk * 8;
            uint32_t aF[4][4], bF[4][2];
#pragma unroll
            for (int mt = 0; mt < 4; mt++) {
                const int r = wm * 64 + mt * 16;
                aF[mt][0] = __float_as_uint(As[r + g][kb + tig]);
                aF[mt][1] = __float_as_uint(As[r + g + 8][kb + tig]);
                aF[mt][2] = __float_as_uint(As[r + g][kb + tig + 4]);
                aF[mt][3] = __float_as_uint(As[r + g + 8][kb + tig + 4]);
            }
#pragma unroll
            for (int nt = 0; nt < 4; nt++) {
                const int cn = wn * 32 + nt * 8 + g;
                bF[nt][0] = __float_as_uint(Bs[cn][kb + tig]);
                bF[nt][1] = __float_as_uint(Bs[cn][kb + tig + 4]);
            }
#pragma unroll
            for (int mt = 0; mt < 4; mt++)
#pragma unroll
                for (int nt = 0; nt < 4; nt++)
                    mma_tf32(c[mt][nt], aF[mt], bF[nt]);
        }
        __syncthreads();
    }

    float* gb = sm;  // stride 66, 128x66 region
    if (wn < 2) {
#pragma unroll
        for (int mt = 0; mt < 4; mt++) {
            int r0 = wm * 64 + mt * 16 + g;
#pragma unroll
            for (int nt = 0; nt < 4; nt++) {
                int cn = wn * 32 + nt * 8 + tig * 2;
                gb[r0 * 66 + cn] = c[mt][nt].x;
                gb[r0 * 66 + cn + 1] = c[mt][nt].y;
                gb[(r0 + 8) * 66 + cn] = c[mt][nt].z;
                gb[(r0 + 8) * 66 + cn + 1] = c[mt][nt].w;
            }
        }
    }
    __syncthreads();
    if (wn >= 2) {
#pragma unroll
        for (int mt = 0; mt < 4; mt++) {
            int r0 = wm * 64 + mt * 16 + g;
#pragma unroll
            for (int nt = 0; nt < 4; nt++) {
                int s = (wn - 2) * 32 + nt * 8 + tig * 2;
                float2 bgv = *(const float2*)(bg + s);
                float g0 = 1.f / (1.f + __expf(-(gb[r0 * 66 + s] + bgv.x)));
                float g1 = 1.f / (1.f + __expf(-(gb[r0 * 66 + s + 1] + bgv.y)));
                float g2 = 1.f / (1.f + __expf(-(gb[(r0 + 8) * 66 + s] + bgv.x)));
                float g3 = 1.f / (1.f + __expf(-(gb[(r0 + 8) * 66 + s + 1] + bgv.y)));
                float2 u0 = {g0 * c[mt][nt].x, g1 * c[mt][nt].y};
                float2 u1 = {g2 * c[mt][nt].z, g3 * c[mt][nt].w};
                *(float2*)(g_u + (size_t)(m0 + r0) * 64 + s) = u0;
                *(float2*)(g_u + (size_t)(m0 + r0 + 8) * 64 + s) = u1;
            }
        }
    }
}

// ---------------- K2: local chunk scans (in-place on g_u) ---------------------
__global__ void k_scan(const float* __restrict__ A_log) {
    int b = blockIdx.x >> 7;
    int c = blockIdx.x & 127;
    int s = threadIdx.x;
    float A = expf(A_log[s]);
    float* base = g_u + (size_t)(b * Tn + c * CH) * Sn + s;
    float st = 0.f;
#pragma unroll
    for (int j = 0; j < CH; j++) {
        st = fmaf(A, st, base[j * 64]);
        base[j * 64] = st;
    }
    g_last[(b * NCH + c) * Sn + s] = st;
}

// ---------------- K2b: parallel affine scan over chunks (Kogge-Stone) ---------
__global__ void __launch_bounds__(128) k_carry(float* __restrict__ out_tail,
                                               int write_tail) {
    __shared__ float wtot[4], wp[4];
    const int chain = blockIdx.x;
    const int b = chain >> 6, s = chain & 63;
    const int c = threadIdx.x;
    const int lane = c & 31, warp = c >> 5;

    const float AC = g_decay[(CH - 1) * Sn + s];
    float v = g_last[(b * NCH + c) * Sn + s];
    float p = AC;
#pragma unroll
    for (int off = 1; off < 32; off <<= 1) {
        float pv = __shfl_up_sync(0xffffffffu, v, off);
        float pp = __shfl_up_sync(0xffffffffu, p, off);
        if (lane >= off) { v = fmaf(p, pv, v); p *= pp; }
    }
    if (lane == 31) { wtot[warp] = v; wp[warp] = p; }
    __syncthreads();
    float cin = 0.f;
#pragma unroll
    for (int w = 0; w < 3; w++)
        if (w < warp) cin = fmaf(wp[w], cin, wtot[w]);
    float inc = fmaf(p, cin, v);
    float prev = __shfl_up_sync(0xffffffffu, inc, 1);
    float carry_c = (lane == 0) ? cin : prev;
    g_carry[(b * NCH + c) * Sn + s] = carry_c;
    if (c == NCH - 1 && write_tail) out_tail[b * Sn + s] = inc;
}

// ---------------- K3: states fixup -> y -> LN -> g_hnh (fp16) -----------------
__global__ void __launch_bounds__(256) k_y_ln(const float* __restrict__ x,
                                              const float* __restrict__ D,
                                              const float* __restrict__ gamma,
                                              const float* __restrict__ beta) {
    __shared__ float sst[16][64];
    __shared__ float ssum[16][8], ssq[16][8];
    const int tid = threadIdx.x;
    const int bt0 = blockIdx.x * 16;

#pragma unroll
    for (int li = 0; li < 4; li++) {
        int idx = tid + li * 256;
        int t = idx >> 6, s = idx & 63;
        int gt = bt0 + t;
        int b = gt >> 12;
        int tt = gt & (Tn - 1);
        int c = tt >> 5, j = tt & (CH - 1);
        float v = g_u[(size_t)gt * 64 + s] + g_decay[j * 64 + s] * g_carry[(b * NCH + c) * 64 + s];
        sst[t][s] = v;
    }
    __syncthreads();

    const int h0 = tid * 4;
    float4 acc[16];
#pragma unroll
    for (int t = 0; t < 16; t++) acc[t] = make_float4(0.f, 0.f, 0.f, 0.f);

    const float4* wct4 = (const float4*)g_wct;
    float4 wc = wct4[tid];
#pragma unroll 1
    for (int s = 0; s < 64; s++) {
        float4 wcn = wc;
        if (s < 63) wcn = wct4[(s + 1) * 256 + tid];
#pragma unroll
        for (int t = 0; t < 16; t++) {
            float f = sst[t][s];
            acc[t].x = fmaf(f, wc.x, acc[t].x);
            acc[t].y = fmaf(f, wc.y, acc[t].y);
            acc[t].z = fmaf(f, wc.z, acc[t].z);
            acc[t].w = fmaf(f, wc.w, acc[t].w);
        }
        wc = wcn;
    }

    const float4 D4 = *(const float4*)(D + h0);
    const float4 g4 = *(const float4*)(gamma + h0);
    const float4 b4 = *(const float4*)(beta + h0);
    const int lane = tid & 31, warp = tid >> 5;

#pragma unroll
    for (int t = 0; t < 16; t++) {
        int gt = bt0 + t;
        float4 xv = *(const float4*)(x + (size_t)gt * Hn + h0);
        float4 hv;
        hv.x = acc[t].x + (D4.x + 1.f) * xv.x;
        hv.y = acc[t].y + (D4.y + 1.f) * xv.y;
        hv.z = acc[t].z + (D4.z + 1.f) * xv.z;
        hv.w = acc[t].w + (D4.w + 1.f) * xv.w;
        acc[t] = hv;
        float s1 = hv.x + hv.y + hv.z + hv.w;
        float s2 = hv.x * hv.x + hv.y * hv.y + hv.z * hv.z + hv.w * hv.w;
#pragma unroll
        for (int off = 16; off; off >>= 1) {
            s1 += __shfl_xor_sync(0xffffffffu, s1, off);
            s2 += __shfl_xor_sync(0xffffffffu, s2, off);
        }
        if (lane == 0) { ssum[t][warp] = s1; ssq[t][warp] = s2; }
    }
    __syncthreads();

#pragma unroll
    for (int t = 0; t < 16; t++) {
        float S1 = 0.f, S2 = 0.f;
#pragma unroll
        for (int w = 0; w < 8; w++) { S1 += ssum[t][w]; S2 += ssq[t][w]; }
        float mu = S1 * (1.f / 1024.f);
        float var = S2 * (1.f / 1024.f) - mu * mu;
        float rs = rsqrtf(var + 1e-5f);
        float4 hv = acc[t];
        __half2 o01 = __floats2half2_rn((hv.x - mu) * rs * g4.x + b4.x,
                                        (hv.y - mu) * rs * g4.y + b4.y);
        __half2 o23 = __floats2half2_rn((hv.z - mu) * rs * g4.z + b4.z,
                                        (hv.w - mu) * rs * g4.w + b4.w);
        uint2 pk;
        pk.x = *(uint32_t*)&o01;
        pk.y = *(uint32_t*)&o23;
        *(uint2*)(g_hnh + (size_t)(bt0 + t) * Hn + h0) = pk;
    }
}

// ---------------- K4: out = hn @ Wout^T + bout  (fp16 mma, 4-stage cp.async) --
// BM=128, BN=128, BK=32 halves (64B/row). m16n8k16 f16 mma, f32 accumulate.
constexpr int PADH = 40;                             // halves per row (80B)
constexpr int KSTG = 4;
constexpr int STG_H = 2 * 128 * PADH;                // halves per stage (A+B)
constexpr int SMEM_KOUT = KSTG * STG_H * 2;          // 81920 bytes
__global__ void __launch_bounds__(256) k_out(const float* __restrict__ bout,
                                             float* __restrict__ out) {
    extern __shared__ __half smk[];
    const int tid = threadIdx.x;
    const int lane = tid & 31, warp = tid >> 5;
    const int g = lane >> 2, tig = lane & 3;
    const int wm = warp >> 2, wn = warp & 3;
    const int m0 = blockIdx.y * 128, n0 = blockIdx.x * 128;

    // tile = 128 rows x 4 16B-segments = 512 cp16 per operand; 2 per thread
    const int r_a = tid >> 1;                 // 0..127
    const int sg2 = (tid & 1) * 2;            // segments {0,1} or {2,3}

    float4 c[4][4];
#pragma unroll
    for (int mt = 0; mt < 4; mt++)
#pragma unroll
        for (int nt = 0; nt < 4; nt++) c[mt][nt] = make_float4(0.f, 0.f, 0.f, 0.f);

    auto issue = [&](int st, int k0) {
        __half* A = smk + st * STG_H;
        __half* B = A + 128 * PADH;
        const __half* Ag = g_hnh + (size_t)(m0 + r_a) * Hn + k0;
        const __half* Bg = g_wouth + (size_t)(n0 + r_a) * Hn + k0;
#pragma unroll
        for (int s = 0; s < 2; s++) {
            int seg = sg2 + s;
            cp16(A + r_a * PADH + seg * 8, Ag + seg * 8);
            cp16(B + r_a * PADH + seg * 8, Bg + seg * 8);
        }
        cp_commit();
    };

    issue(0, 0);
    issue(1, 32);
    issue(2, 64);
    constexpr int NT = Hn / 32;   // 32 K-tiles
    for (int kt = 0; kt < NT; kt++) {
        asm volatile("cp.async.wait_group 2;");
        __syncthreads();
        const int st = kt & 3;
        const __half* A = smk + st * STG_H;
        const __half* B = A + 128 * PADH;
#pragma unroll
        for (int kk = 0; kk < 2; kk++) {
            const int kb = kk * 16;
            uint32_t aF[4][4], bF[4][2];
#pragma unroll
            for (int mt = 0; mt < 4; mt++) {
                const int r = wm * 64 + mt * 16;
                aF[mt][0] = *(const uint32_t*)&A[(r + g) * PADH + kb + 2 * tig];
                aF[mt][1] = *(const uint32_t*)&A[(r + g + 8) * PADH + kb + 2 * tig];
                aF[mt][2] = *(const uint32_t*)&A[(r + g) * PADH + kb + 2 * tig + 8];
                aF[mt][3] = *(const uint32_t*)&A[(r + g + 8) * PADH + kb + 2 * tig + 8];
            }
#pragma unroll
            for (int nt = 0; nt < 4; nt++) {
                const int cn = wn * 32 + nt * 8 + g;
                bF[nt][0] = *(const uint32_t*)&B[cn * PADH + kb + 2 * tig];
                bF[nt][1] = *(const uint32_t*)&B[cn * PADH + kb + 2 * tig + 8];
            }
#pragma unroll
            for (int mt = 0; mt < 4; mt++)
#pragma unroll
                for (int nt = 0; nt < 4; nt++)
                    mma_f16(c[mt][nt], aF[mt], bF[nt]);
        }
        if (kt + 3 < NT) issue((kt + 3) & 3, (kt + 3) * 32);
        else cp_commit();   // empty group keeps wait_group accounting aligned
    }

#pragma unroll
    for (int mt = 0; mt < 4; mt++) {
        int r0 = m0 + wm * 64 + mt * 16 + g;
#pragma unroll
        for (int nt = 0; nt < 4; nt++) {
            int cn = n0 + wn * 32 + nt * 8 + tig * 2;
            float2 bo = *(const float2*)(bout + cn);
            float2 o0 = {c[mt][nt].x + bo.x, c[mt][nt].y + bo.y};
            float2 o1 = {c[mt][nt].z + bo.x, c[mt][nt].w + bo.y};
            *(float2*)(out + (size_t)r0 * Hn + cn) = o0;
            *(float2*)(out + (size_t)(r0 + 8) * Hn + cn) = o1;
        }
    }
}

// ---------------- launch ------------------------------------------------------
extern "C" void kernel_launch(void* const* d_in, const int* in_sizes, int n_in,
                              void* d_out, int out_size) {
    const float* x     = (const float*)d_in[0];
    const float* A_log = (const float*)d_in[1];
    const float* WB    = (const float*)d_in[2];
    const float* WC    = (const float*)d_in[3];
    const float* D     = (const float*)d_in[4];
    const float* Wg    = (const float*)d_in[5];
    const float* bg    = (const float*)d_in[6];
    const float* Wout  = (const float*)d_in[7];
    const float* bout  = (const float*)d_in[8];
    const float* gamma = (const float*)d_in[9];
    const float* beta  = (const float*)d_in[10];
    float* out = (float*)d_out;

    cudaFuncSetAttribute(k_out, cudaFuncAttributeMaxDynamicSharedMemorySize, SMEM_KOUT);

    k_prep<<<4096, 256>>>(WC, A_log, Wout);
    k_proj<<<Mn / 128, 256>>>(x, Wg, WB, bg);
    k_scan<<<Bn * NCH, 64>>>(A_log);
    int wt = (out_size >= Mn * Hn + Bn * Sn) ? 1 : 0;
    k_carry<<<Bn * Sn, 128>>>(out + (size_t)Mn * Hn, wt);
    k_y_ln<<<Mn / 16, 256>>>(x, D, gamma, beta);
    k_out<<<dim3(Hn / 128, Mn / 128), 256, SMEM_KOUT>>>(bout, out);
}